// round 1
// baseline (speedup 1.0000x reference)
#include <cuda_runtime.h>

#define NN   50000
#define EE   800000
#define DIN  128
#define HH   64
#define PB   120   // pool partial blocks (fixed => deterministic)

// ---------------- scratch (static device globals: no allocation) -------------
__device__ int   g_deg[NN];
__device__ int   g_cursor[NN];
__device__ int   g_rowptr[NN + 1];
__device__ float g_dinv[NN];
__device__ int   g_col[EE];
__device__ float g_val[EE];
__device__ float g_hA[(size_t)NN * HH];
__device__ float g_hB[(size_t)NN * HH];
__device__ float g_psum[PB * HH];
__device__ float g_pmax[PB * HH];

// ---------------- setup kernels ----------------------------------------------
__global__ void init_kernel() {
    int i = blockIdx.x * blockDim.x + threadIdx.x;
    if (i < NN) { g_deg[i] = 0; g_cursor[i] = 0; }
    if (i == 0) g_rowptr[NN] = EE;
}

__global__ void count_kernel(const int* __restrict__ ei) {
    int e = blockIdx.x * blockDim.x + threadIdx.x;
    if (e < EE) atomicAdd(&g_deg[ei[EE + e]], 1);   // dst = ei[1][e]
}

__global__ void dinv_kernel() {
    int i = blockIdx.x * blockDim.x + threadIdx.x;
    if (i < NN) g_dinv[i] = rsqrtf((float)g_deg[i] + 1.0f);
}

// single-block exclusive scan of g_deg -> g_rowptr
__global__ void scan_kernel() {
    __shared__ int sm[1024];
    const int t  = threadIdx.x;
    const int CH = (NN + 1023) / 1024;        // 49
    int lo = t * CH, hi = min(lo + CH, NN);
    int s = 0;
    for (int i = lo; i < hi; i++) s += g_deg[i];
    sm[t] = s;
    __syncthreads();
    for (int off = 1; off < 1024; off <<= 1) {
        int v = (t >= off) ? sm[t - off] : 0;
        __syncthreads();
        sm[t] += v;
        __syncthreads();
    }
    int run = sm[t] - s;                      // exclusive prefix
    for (int i = lo; i < hi; i++) { g_rowptr[i] = run; run += g_deg[i]; }
}

__global__ void scatter_kernel(const int* __restrict__ ei) {
    int e = blockIdx.x * blockDim.x + threadIdx.x;
    if (e >= EE) return;
    int s = ei[e];
    int d = ei[EE + e];
    int p = g_rowptr[d] + atomicAdd(&g_cursor[d], 1);
    g_col[p] = s;
    g_val[p] = g_dinv[s];
}

// ---------------- GEMM: Y[N,64] = X[N,K] @ W[K,64] ---------------------------
// one thread per row, 64 fp32 accumulators, W broadcast from smem (LDS.128).
template <int K>
__global__ __launch_bounds__(128) void gemm_kernel(const float* __restrict__ X,
                                                   const float* __restrict__ W,
                                                   float* __restrict__ Y,
                                                   int nrows) {
    __shared__ float4 Wsm[K * 16];            // K x 64 floats
    for (int i = threadIdx.x; i < K * 16; i += 128)
        Wsm[i] = reinterpret_cast<const float4*>(W)[i];
    __syncthreads();

    int row = blockIdx.x * 128 + threadIdx.x;
    if (row >= nrows) return;

    const float4* xp = reinterpret_cast<const float4*>(X + (size_t)row * K);
    float4 acc[16];
#pragma unroll
    for (int c = 0; c < 16; c++) acc[c] = make_float4(0.f, 0.f, 0.f, 0.f);

#pragma unroll 1
    for (int kc = 0; kc < K / 16; kc++) {
        float4 xv[4];
#pragma unroll
        for (int j = 0; j < 4; j++) xv[j] = xp[kc * 4 + j];
#pragma unroll
        for (int j = 0; j < 4; j++) {
            const float xs[4] = {xv[j].x, xv[j].y, xv[j].z, xv[j].w};
#pragma unroll
            for (int q = 0; q < 4; q++) {
                const float s = xs[q];
                const int   k = kc * 16 + j * 4 + q;
#pragma unroll
                for (int c = 0; c < 16; c++) {
                    float4 w = Wsm[k * 16 + c];
                    acc[c].x = fmaf(s, w.x, acc[c].x);
                    acc[c].y = fmaf(s, w.y, acc[c].y);
                    acc[c].z = fmaf(s, w.z, acc[c].z);
                    acc[c].w = fmaf(s, w.w, acc[c].w);
                }
            }
        }
    }

    float4* yp = reinterpret_cast<float4*>(Y + (size_t)row * HH);
#pragma unroll
    for (int c = 0; c < 16; c++) yp[c] = acc[c];
}

// ---------------- aggregation: one warp per node (CSR gather) ----------------
// out[i] = relu( dinv[i]*sum_j dinv[src_j]*h[src_j] + dinv[i]^2*h[i] + b )
__global__ void agg_kernel(const float* __restrict__ hin,
                           const float* __restrict__ bias,
                           float* __restrict__ hout) {
    int warp = threadIdx.x >> 5;
    int lane = threadIdx.x & 31;
    int row  = blockIdx.x * 8 + warp;
    if (row >= NN) return;

    int start = g_rowptr[row];
    int end   = g_rowptr[row + 1];

    float a0 = 0.f, a1 = 0.f;
    for (int p = start; p < end; p++) {
        int   s = g_col[p];
        float w = g_val[p];
        const float* hr = hin + (size_t)s * HH;
        a0 = fmaf(w, hr[lane], a0);
        a1 = fmaf(w, hr[lane + 32], a1);
    }
    float di  = g_dinv[row];
    float di2 = di * di;
    const float* hs = hin + (size_t)row * HH;
    float o0 = fmaf(a0, di, fmaf(di2, hs[lane],      bias[lane]));
    float o1 = fmaf(a1, di, fmaf(di2, hs[lane + 32], bias[lane + 32]));
    float* ho = hout + (size_t)row * HH;
    ho[lane]      = fmaxf(o0, 0.f);
    ho[lane + 32] = fmaxf(o1, 0.f);
}

// ---------------- pooling: deterministic 2-stage mean+max --------------------
__global__ void pool_kernel(const float* __restrict__ h) {
    __shared__ float ss[256], sm[256];
    int tid = threadIdx.x;
    int c   = tid & 63;
    int rg  = tid >> 6;                       // 0..3
    float s = 0.f, m = 0.f;                   // h >= 0 (post-relu)
    for (int r = blockIdx.x * 4 + rg; r < NN; r += PB * 4) {
        float v = h[(size_t)r * HH + c];
        s += v;
        m = fmaxf(m, v);
    }
    ss[tid] = s; sm[tid] = m;
    __syncthreads();
    if (tid < 64) {
        float S = ss[tid] + ss[tid + 64] + ss[tid + 128] + ss[tid + 192];
        float M = fmaxf(fmaxf(sm[tid], sm[tid + 64]),
                        fmaxf(sm[tid + 128], sm[tid + 192]));
        g_psum[blockIdx.x * 64 + tid] = S;
        g_pmax[blockIdx.x * 64 + tid] = M;
    }
}

__global__ void head_kernel(const float* __restrict__ fw1,
                            const float* __restrict__ fb1,
                            const float* __restrict__ fw2,
                            const float* __restrict__ fb2,
                            float* __restrict__ out) {
    __shared__ float pooled[128];
    __shared__ float red[64];
    int tid = threadIdx.x;                    // 64 threads
    float s = 0.f, m = 0.f;
    for (int b = 0; b < PB; b++) {
        s += g_psum[b * 64 + tid];
        m  = fmaxf(m, g_pmax[b * 64 + tid]);
    }
    pooled[tid]      = s * (1.0f / NN);       // mean
    pooled[tid + 64] = m;                     // max
    __syncthreads();

    float acc = fb1[tid];
#pragma unroll 4
    for (int k = 0; k < 128; k++) acc = fmaf(pooled[k], fw1[k * 64 + tid], acc);
    red[tid] = fmaxf(acc, 0.f) * fw2[tid];
    __syncthreads();
    if (tid == 0) {
        float t = 0.f;
        for (int i = 0; i < 64; i++) t += red[i];
        out[0] = t + fb2[0];
    }
}

// ---------------- launcher ---------------------------------------------------
extern "C" void kernel_launch(void* const* d_in, const int* in_sizes, int n_in,
                              void* d_out, int out_size) {
    const float* x   = (const float*)d_in[0];
    const int*   ei  = (const int*)d_in[1];
    const float* W1  = (const float*)d_in[2];
    const float* b1  = (const float*)d_in[3];
    const float* W2  = (const float*)d_in[4];
    const float* b2  = (const float*)d_in[5];
    const float* W3  = (const float*)d_in[6];
    const float* b3  = (const float*)d_in[7];
    const float* fw1 = (const float*)d_in[8];
    const float* fb1 = (const float*)d_in[9];
    const float* fw2 = (const float*)d_in[10];
    const float* fb2 = (const float*)d_in[11];
    float* out = (float*)d_out;

    float *hA, *hB;
    cudaGetSymbolAddress((void**)&hA, g_hA);
    cudaGetSymbolAddress((void**)&hB, g_hB);

    const int NB_N = (NN + 255) / 256;        // 196
    const int NB_E = (EE + 255) / 256;        // 3125

    init_kernel<<<NB_N, 256>>>();
    count_kernel<<<NB_E, 256>>>(ei);
    dinv_kernel<<<NB_N, 256>>>();
    scan_kernel<<<1, 1024>>>();
    scatter_kernel<<<NB_E, 256>>>(ei);

    const int GB = (NN + 127) / 128;          // 391
    const int AB = (NN + 7) / 8;              // 6250

    gemm_kernel<DIN><<<GB, 128>>>(x,  W1, hA, NN);
    agg_kernel<<<AB, 256>>>(hA, b1, hB);
    gemm_kernel<HH><<<GB, 128>>>(hB, W2, hA, NN);
    agg_kernel<<<AB, 256>>>(hA, b2, hB);
    gemm_kernel<HH><<<GB, 128>>>(hB, W3, hA, NN);
    agg_kernel<<<AB, 256>>>(hA, b3, hB);

    pool_kernel<<<PB, 256>>>(hB);
    head_kernel<<<1, 64>>>(fw1, fb1, fw2, fb2, out);
}

// round 2
// speedup vs baseline: 1.2154x; 1.2154x over previous
#include <cuda_runtime.h>

#define NN   50000
#define EE   800000
#define DIN  128
#define HH   64
#define PB   120   // pool partial blocks (fixed => deterministic)

// ---------------- scratch (static device globals: no allocation) -------------
__device__ int   g_deg[NN];
__device__ int   g_cursor[NN];
__device__ int2  g_row[NN];          // (rowstart, deg)
__device__ int   g_tot;
__device__ float g_dinv[NN];
__device__ int2  g_colval[EE];       // (src, __float_as_int(dinv[src]))
__device__ float g_hA[(size_t)NN * HH];
__device__ float g_hB[(size_t)NN * HH];
__device__ float g_psum[PB * HH];
__device__ float g_pmax[PB * HH];

typedef unsigned long long u64;

__device__ __forceinline__ void ffma2(u64& d, u64 a, u64 b) {
    asm("fma.rn.f32x2 %0, %1, %2, %0;" : "+l"(d) : "l"(a), "l"(b));
}
__device__ __forceinline__ u64 pack2(float lo, float hi) {
    u64 r; asm("mov.b64 %0, {%1, %2};" : "=l"(r) : "f"(lo), "f"(hi)); return r;
}
__device__ __forceinline__ void unpack2(float& lo, float& hi, u64 v) {
    asm("mov.b64 {%0, %1}, %2;" : "=f"(lo), "=f"(hi) : "l"(v));
}

// ---------------- setup kernels ----------------------------------------------
__global__ void init_kernel() {
    int i = blockIdx.x * blockDim.x + threadIdx.x;
    if (i < NN) { g_deg[i] = 0; g_cursor[i] = 0; }
    if (i == 0) g_tot = 0;
}

__global__ void count_kernel(const int* __restrict__ ei) {
    int e = blockIdx.x * blockDim.x + threadIdx.x;
    if (e < EE) atomicAdd(&g_deg[ei[EE + e]], 1);   // dst = ei[1][e]
}

// warp-aggregated segment allocator + dinv (replaces the 47us single-block scan)
__global__ void alloc_kernel() {
    int i    = blockIdx.x * blockDim.x + threadIdx.x;
    int lane = threadIdx.x & 31;
    int d    = (i < NN) ? g_deg[i] : 0;

    // warp inclusive scan of d
    int x = d;
#pragma unroll
    for (int off = 1; off < 32; off <<= 1) {
        int v = __shfl_up_sync(0xFFFFFFFFu, x, off);
        if (lane >= off) x += v;
    }
    int wsum = __shfl_sync(0xFFFFFFFFu, x, 31);
    int base = 0;
    if (lane == 31) base = atomicAdd(&g_tot, wsum);
    base = __shfl_sync(0xFFFFFFFFu, base, 31);

    if (i < NN) {
        g_row[i]  = make_int2(base + x - d, d);
        g_dinv[i] = rsqrtf((float)d + 1.0f);
    }
}

__global__ void scatter_kernel(const int* __restrict__ ei) {
    int e = blockIdx.x * blockDim.x + threadIdx.x;
    if (e >= EE) return;
    int s = ei[e];
    int d = ei[EE + e];
    int p = g_row[d].x + atomicAdd(&g_cursor[d], 1);
    g_colval[p] = make_int2(s, __float_as_int(g_dinv[s]));
}

// ---------------- GEMM: Y[N,64] = X[N,K] @ W[K,64] ---------------------------
// one thread per row, 32 packed f32x2 accumulators, W broadcast from smem.
template <int K>
__global__ __launch_bounds__(128) void gemm_kernel(const float* __restrict__ X,
                                                   const float* __restrict__ W,
                                                   float* __restrict__ Y,
                                                   int nrows) {
    __shared__ ulonglong2 Wsm[K * 16];        // K x 64 floats as 16B chunks
    for (int i = threadIdx.x; i < K * 16; i += 128)
        Wsm[i] = reinterpret_cast<const ulonglong2*>(W)[i];
    __syncthreads();

    int row = blockIdx.x * 128 + threadIdx.x;
    if (row >= nrows) return;

    const float4* xp = reinterpret_cast<const float4*>(X + (size_t)row * K);
    u64 acc[32];
#pragma unroll
    for (int c = 0; c < 32; c++) acc[c] = 0ull;   // (0.f, 0.f)

#pragma unroll 1
    for (int kc = 0; kc < K / 16; kc++) {
        float4 xv[4];
#pragma unroll
        for (int j = 0; j < 4; j++) xv[j] = xp[kc * 4 + j];
#pragma unroll
        for (int j = 0; j < 4; j++) {
            const float xs[4] = {xv[j].x, xv[j].y, xv[j].z, xv[j].w};
#pragma unroll
            for (int q = 0; q < 4; q++) {
                const u64 ss = pack2(xs[q], xs[q]);
                const int k  = kc * 16 + j * 4 + q;
#pragma unroll
                for (int c = 0; c < 16; c++) {
                    ulonglong2 w = Wsm[k * 16 + c];
                    ffma2(acc[2 * c],     ss, w.x);
                    ffma2(acc[2 * c + 1], ss, w.y);
                }
            }
        }
    }

    ulonglong2* yp = reinterpret_cast<ulonglong2*>(Y + (size_t)row * HH);
#pragma unroll
    for (int c = 0; c < 16; c++) yp[c] = make_ulonglong2(acc[2 * c], acc[2 * c + 1]);
}

// ---------------- aggregation: one warp per node (CSR gather) ----------------
// out[i] = relu( dinv[i]*sum_j dinv[src_j]*h[src_j] + dinv[i]^2*h[i] + b )
__global__ void agg_kernel(const float* __restrict__ hin,
                           const float* __restrict__ bias,
                           float* __restrict__ hout) {
    int warp = threadIdx.x >> 5;
    int lane = threadIdx.x & 31;
    int row  = blockIdx.x * 8 + warp;
    if (row >= NN) return;

    int2 rd    = g_row[row];
    int  start = rd.x;
    int  end   = rd.x + rd.y;

    u64 acc = 0ull;
    for (int p = start; p < end; p++) {
        int2 cv = g_colval[p];
        u64  w  = pack2(__int_as_float(cv.y), __int_as_float(cv.y));
        u64  h2 = reinterpret_cast<const u64*>(hin + (size_t)cv.x * HH)[lane];
        ffma2(acc, w, h2);
    }
    float di  = g_dinv[row];
    float di2 = di * di;
    u64 hs = reinterpret_cast<const u64*>(hin + (size_t)row * HH)[lane];
    u64 bb = reinterpret_cast<const u64*>(bias)[lane];
    // o = acc*di + hs*di2 + b
    u64 o = bb;
    ffma2(o, pack2(di2, di2), hs);
    ffma2(o, pack2(di, di), acc);
    float lo, hi;
    unpack2(lo, hi, o);
    u64 r = pack2(fmaxf(lo, 0.f), fmaxf(hi, 0.f));
    reinterpret_cast<u64*>(hout + (size_t)row * HH)[lane] = r;
}

// ---------------- pooling: deterministic 2-stage mean+max --------------------
__global__ void pool_kernel(const float* __restrict__ h) {
    __shared__ float ss[256], sm[256];
    int tid = threadIdx.x;
    int c   = tid & 63;
    int rg  = tid >> 6;                       // 0..3
    float s = 0.f, m = 0.f;                   // h >= 0 (post-relu)
    for (int r = blockIdx.x * 4 + rg; r < NN; r += PB * 4) {
        float v = h[(size_t)r * HH + c];
        s += v;
        m = fmaxf(m, v);
    }
    ss[tid] = s; sm[tid] = m;
    __syncthreads();
    if (tid < 64) {
        float S = ss[tid] + ss[tid + 64] + ss[tid + 128] + ss[tid + 192];
        float M = fmaxf(fmaxf(sm[tid], sm[tid + 64]),
                        fmaxf(sm[tid + 128], sm[tid + 192]));
        g_psum[blockIdx.x * 64 + tid] = S;
        g_pmax[blockIdx.x * 64 + tid] = M;
    }
}

__global__ void head_kernel(const float* __restrict__ fw1,
                            const float* __restrict__ fb1,
                            const float* __restrict__ fw2,
                            const float* __restrict__ fb2,
                            float* __restrict__ out) {
    __shared__ float pooled[128];
    __shared__ float red[64];
    int tid = threadIdx.x;                    // 64 threads
    float s = 0.f, m = 0.f;
    for (int b = 0; b < PB; b++) {
        s += g_psum[b * 64 + tid];
        m  = fmaxf(m, g_pmax[b * 64 + tid]);
    }
    pooled[tid]      = s * (1.0f / NN);       // mean
    pooled[tid + 64] = m;                     // max
    __syncthreads();

    float acc = fb1[tid];
#pragma unroll 4
    for (int k = 0; k < 128; k++) acc = fmaf(pooled[k], fw1[k * 64 + tid], acc);
    red[tid] = fmaxf(acc, 0.f) * fw2[tid];
    __syncthreads();
    if (tid == 0) {
        float t = 0.f;
        for (int i = 0; i < 64; i++) t += red[i];
        out[0] = t + fb2[0];
    }
}

// ---------------- launcher ---------------------------------------------------
extern "C" void kernel_launch(void* const* d_in, const int* in_sizes, int n_in,
                              void* d_out, int out_size) {
    const float* x   = (const float*)d_in[0];
    const int*   ei  = (const int*)d_in[1];
    const float* W1  = (const float*)d_in[2];
    const float* b1  = (const float*)d_in[3];
    const float* W2  = (const float*)d_in[4];
    const float* b2  = (const float*)d_in[5];
    const float* W3  = (const float*)d_in[6];
    const float* b3  = (const float*)d_in[7];
    const float* fw1 = (const float*)d_in[8];
    const float* fb1 = (const float*)d_in[9];
    const float* fw2 = (const float*)d_in[10];
    const float* fb2 = (const float*)d_in[11];
    float* out = (float*)d_out;

    float *hA, *hB;
    cudaGetSymbolAddress((void**)&hA, g_hA);
    cudaGetSymbolAddress((void**)&hB, g_hB);

    const int NB_N = (NN + 255) / 256;        // 196
    const int NB_E = (EE + 255) / 256;        // 3125

    init_kernel<<<NB_N, 256>>>();
    count_kernel<<<NB_E, 256>>>(ei);
    alloc_kernel<<<NB_N, 256>>>();
    scatter_kernel<<<NB_E, 256>>>(ei);

    const int GB = (NN + 127) / 128;          // 391
    const int AB = (NN + 7) / 8;              // 6250

    gemm_kernel<DIN><<<GB, 128>>>(x,  W1, hA, NN);
    agg_kernel<<<AB, 256>>>(hA, b1, hB);
    gemm_kernel<HH><<<GB, 128>>>(hB, W2, hA, NN);
    agg_kernel<<<AB, 256>>>(hA, b2, hB);
    gemm_kernel<HH><<<GB, 128>>>(hB, W3, hA, NN);
    agg_kernel<<<AB, 256>>>(hA, b3, hB);

    pool_kernel<<<PB, 256>>>(hB);
    head_kernel<<<1, 64>>>(fw1, fb1, fw2, fb2, out);
}

// round 3
// speedup vs baseline: 1.2850x; 1.0572x over previous
#include <cuda_runtime.h>
#include <cuda_fp16.h>

#define NN   50000
#define EE   800000
#define DIN  128
#define HH   64
#define AB   6250            // agg blocks: 8 rows x 6250 = 50000 exactly

// ---------------- scratch (static device globals: no allocation) -------------
__device__ int    g_deg[NN];
__device__ int2   g_row[NN];                 // (rowstart, deg)
__device__ int    g_tot;
__device__ float  g_dinv[NN];
__device__ int    g_rank[EE];                // edge rank within dst segment
__device__ int    g_col[EE];                 // src node per CSR slot
__device__ __align__(16) __half g_hH[(size_t)NN * HH];   // gemm out: dinv*h, fp16
__device__ __align__(16) float  g_hA[(size_t)NN * HH];   // agg out, fp32
__device__ float2 g_psT[32 * AB];            // pool sum partials [lanecol][blk]
__device__ float2 g_pmT[32 * AB];            // pool max partials
__device__ float  g_poolS[HH];
__device__ float  g_poolM[HH];

typedef unsigned long long u64;

__device__ __forceinline__ void ffma2(u64& d, u64 a, u64 b) {
    asm("fma.rn.f32x2 %0, %1, %2, %0;" : "+l"(d) : "l"(a), "l"(b));
}
__device__ __forceinline__ u64 pack2(float lo, float hi) {
    u64 r; asm("mov.b64 %0, {%1, %2};" : "=l"(r) : "f"(lo), "f"(hi)); return r;
}
__device__ __forceinline__ void unpack2(float& lo, float& hi, u64 v) {
    asm("mov.b64 {%0, %1}, %2;" : "=f"(lo), "=f"(hi) : "l"(v));
}

// ---------------- setup kernels ----------------------------------------------
__global__ void init_kernel() {
    int i = blockIdx.x * blockDim.x + threadIdx.x;
    if (i < NN) g_deg[i] = 0;
    if (i == 0) g_tot = 0;
}

// histogram; atomic return value doubles as the edge's rank within its segment
__global__ void count_kernel(const int* __restrict__ ei) {
    int i = blockIdx.x * blockDim.x + threadIdx.x;
    if (i >= EE / 4) return;
    int4 d4 = reinterpret_cast<const int4*>(ei + EE)[i];
    int4 r4;
    r4.x = atomicAdd(&g_deg[d4.x], 1);
    r4.y = atomicAdd(&g_deg[d4.y], 1);
    r4.z = atomicAdd(&g_deg[d4.z], 1);
    r4.w = atomicAdd(&g_deg[d4.w], 1);
    reinterpret_cast<int4*>(g_rank)[i] = r4;
}

// warp-aggregated segment allocator + dinv
__global__ void alloc_kernel() {
    int i    = blockIdx.x * blockDim.x + threadIdx.x;
    int lane = threadIdx.x & 31;
    int d    = (i < NN) ? g_deg[i] : 0;

    int x = d;
#pragma unroll
    for (int off = 1; off < 32; off <<= 1) {
        int v = __shfl_up_sync(0xFFFFFFFFu, x, off);
        if (lane >= off) x += v;
    }
    int wsum = __shfl_sync(0xFFFFFFFFu, x, 31);
    int base = 0;
    if (lane == 31) base = atomicAdd(&g_tot, wsum);
    base = __shfl_sync(0xFFFFFFFFu, base, 31);

    if (i < NN) {
        g_row[i]  = make_int2(base + x - d, d);
        g_dinv[i] = rsqrtf((float)d + 1.0f);
    }
}

// atomic-free scatter: slot = rowstart[dst] + rank[e]
__global__ void scatter_kernel(const int* __restrict__ ei) {
    int i = blockIdx.x * blockDim.x + threadIdx.x;
    if (i >= EE / 4) return;
    int4 s4 = reinterpret_cast<const int4*>(ei)[i];
    int4 d4 = reinterpret_cast<const int4*>(ei + EE)[i];
    int4 r4 = reinterpret_cast<const int4*>(g_rank)[i];
    g_col[g_row[d4.x].x + r4.x] = s4.x;
    g_col[g_row[d4.y].x + r4.y] = s4.y;
    g_col[g_row[d4.z].x + r4.z] = s4.z;
    g_col[g_row[d4.w].x + r4.w] = s4.w;
}

// ---------------- GEMM: hH[N,64] = fp16( dinv[i] * (X[N,K] @ W[K,64]) ) ------
// one thread per row, 32 packed f32x2 accumulators, W broadcast from smem.
template <int K>
__global__ __launch_bounds__(128) void gemm_kernel(const float* __restrict__ X,
                                                   const float* __restrict__ W,
                                                   int nrows) {
    __shared__ ulonglong2 Wsm[K * 16];        // K x 64 floats as 16B chunks
    for (int i = threadIdx.x; i < K * 16; i += 128)
        Wsm[i] = reinterpret_cast<const ulonglong2*>(W)[i];
    __syncthreads();

    int row = blockIdx.x * 128 + threadIdx.x;
    if (row >= nrows) return;

    const float4* xp = reinterpret_cast<const float4*>(X + (size_t)row * K);
    u64 acc[32];
#pragma unroll
    for (int c = 0; c < 32; c++) acc[c] = 0ull;

#pragma unroll 1
    for (int kc = 0; kc < K / 16; kc++) {
        float4 xv[4];
#pragma unroll
        for (int j = 0; j < 4; j++) xv[j] = xp[kc * 4 + j];
#pragma unroll
        for (int j = 0; j < 4; j++) {
            const float xs[4] = {xv[j].x, xv[j].y, xv[j].z, xv[j].w};
#pragma unroll
            for (int q = 0; q < 4; q++) {
                const u64 ss = pack2(xs[q], xs[q]);
                const int k  = kc * 16 + j * 4 + q;
#pragma unroll
                for (int c = 0; c < 16; c++) {
                    ulonglong2 w = Wsm[k * 16 + c];
                    ffma2(acc[2 * c],     ss, w.x);
                    ffma2(acc[2 * c + 1], ss, w.y);
                }
            }
        }
    }

    // epilogue: scale by dinv[row], convert to fp16, store 128B row
    float di = g_dinv[row];
    uint4* yp = reinterpret_cast<uint4*>((char*)g_hH + (size_t)row * 128);
#pragma unroll
    for (int c = 0; c < 8; c++) {
        uint4 o;
        unsigned r[4];
#pragma unroll
        for (int q = 0; q < 4; q++) {
            float lo, hi;
            unpack2(lo, hi, acc[4 * c + q]);
            __half2 h = __floats2half2_rn(lo * di, hi * di);
            r[q] = *reinterpret_cast<unsigned*>(&h);
        }
        o.x = r[0]; o.y = r[1]; o.z = r[2]; o.w = r[3];
        yp[c] = o;
    }
}

// ---------------- aggregation: warp per node, fp16 gather --------------------
// A[i] = relu( dinv[i] * (sum_j h'[src_j] + h'[i]) + b ),  h' = dinv*h (fp16)
__device__ __forceinline__ float2 agg_row(int row, int lane) {
    int2 rd = g_row[row];
    const unsigned* hb = reinterpret_cast<const unsigned*>(g_hH);

    float ax = 0.f, ay = 0.f;
    for (int base = 0; base < rd.y; base += 32) {
        int cnt = min(32, rd.y - base);
        int s = (lane < cnt) ? g_col[rd.x + base + lane] : 0;
#pragma unroll 4
        for (int j = 0; j < cnt; j++) {
            int sj = __shfl_sync(0xFFFFFFFFu, s, j);
            unsigned hv = __ldg(hb + sj * 32 + lane);
            float2 f = __half22float2(*reinterpret_cast<__half2*>(&hv));
            ax += f.x; ay += f.y;
        }
    }
    unsigned hs = hb[row * 32 + lane];
    float2 fs = __half22float2(*reinterpret_cast<__half2*>(&hs));
    float di = g_dinv[row];
    return make_float2((ax + fs.x) * di, (ay + fs.y) * di);
}

__global__ void agg_kernel(const float* __restrict__ bias) {
    int warp = threadIdx.x >> 5;
    int lane = threadIdx.x & 31;
    int row  = blockIdx.x * 8 + warp;

    float2 a = agg_row(row, lane);
    float2 b = reinterpret_cast<const float2*>(bias)[lane];
    float2 o = make_float2(fmaxf(a.x + b.x, 0.f), fmaxf(a.y + b.y, 0.f));
    reinterpret_cast<float2*>(g_hA)[row * 32 + lane] = o;
}

// layer-3 agg with fused pooling partials (activations never materialized)
__global__ void agg_pool_kernel(const float* __restrict__ bias) {
    __shared__ float2 s_sum[8][32];
    __shared__ float2 s_max[8][32];
    int warp = threadIdx.x >> 5;
    int lane = threadIdx.x & 31;
    int row  = blockIdx.x * 8 + warp;

    float2 a = agg_row(row, lane);
    float2 b = reinterpret_cast<const float2*>(bias)[lane];
    float2 o = make_float2(fmaxf(a.x + b.x, 0.f), fmaxf(a.y + b.y, 0.f));
    s_sum[warp][lane] = o;
    s_max[warp][lane] = o;
    __syncthreads();

    if (threadIdx.x < 32) {
        float2 S = make_float2(0.f, 0.f), M = make_float2(0.f, 0.f);
#pragma unroll
        for (int w = 0; w < 8; w++) {
            float2 v = s_sum[w][threadIdx.x];
            S.x += v.x; S.y += v.y;
            float2 m = s_max[w][threadIdx.x];
            M.x = fmaxf(M.x, m.x); M.y = fmaxf(M.y, m.y);
        }
        g_psT[threadIdx.x * AB + blockIdx.x] = S;   // transposed: coalesced reduce
        g_pmT[threadIdx.x * AB + blockIdx.x] = M;
    }
}

// collapse 6250 partials per lane-column pair (32 blocks, coalesced reads)
__global__ void pool_reduce_kernel() {
    __shared__ float sx[256], sy[256], mx[256], my[256];
    int c   = blockIdx.x;
    int tid = threadIdx.x;
    float ax = 0.f, ay = 0.f, bx = 0.f, by = 0.f;
    for (int i = tid; i < AB; i += 256) {
        float2 s = g_psT[c * AB + i];
        ax += s.x; ay += s.y;
        float2 m = g_pmT[c * AB + i];
        bx = fmaxf(bx, m.x); by = fmaxf(by, m.y);
    }
    sx[tid] = ax; sy[tid] = ay; mx[tid] = bx; my[tid] = by;
    __syncthreads();
    for (int off = 128; off > 0; off >>= 1) {
        if (tid < off) {
            sx[tid] += sx[tid + off]; sy[tid] += sy[tid + off];
            mx[tid] = fmaxf(mx[tid], mx[tid + off]);
            my[tid] = fmaxf(my[tid], my[tid + off]);
        }
        __syncthreads();
    }
    if (tid == 0) {
        g_poolS[2 * c]     = sx[0]; g_poolS[2 * c + 1] = sy[0];
        g_poolM[2 * c]     = mx[0]; g_poolM[2 * c + 1] = my[0];
    }
}

__global__ void head_kernel(const float* __restrict__ fw1,
                            const float* __restrict__ fb1,
                            const float* __restrict__ fw2,
                            const float* __restrict__ fb2,
                            float* __restrict__ out) {
    __shared__ float pooled[128];
    __shared__ float red[64];
    int tid = threadIdx.x;                    // 64 threads
    pooled[tid]      = g_poolS[tid] * (1.0f / NN);
    pooled[tid + 64] = g_poolM[tid];
    __syncthreads();

    float acc = fb1[tid];
#pragma unroll 4
    for (int k = 0; k < 128; k++) acc = fmaf(pooled[k], fw1[k * 64 + tid], acc);
    red[tid] = fmaxf(acc, 0.f) * fw2[tid];
    __syncthreads();
    if (tid == 0) {
        float t = 0.f;
        for (int i = 0; i < 64; i++) t += red[i];
        out[0] = t + fb2[0];
    }
}

// ---------------- launcher ---------------------------------------------------
extern "C" void kernel_launch(void* const* d_in, const int* in_sizes, int n_in,
                              void* d_out, int out_size) {
    const float* x   = (const float*)d_in[0];
    const int*   ei  = (const int*)d_in[1];
    const float* W1  = (const float*)d_in[2];
    const float* b1  = (const float*)d_in[3];
    const float* W2  = (const float*)d_in[4];
    const float* b2  = (const float*)d_in[5];
    const float* W3  = (const float*)d_in[6];
    const float* b3  = (const float*)d_in[7];
    const float* fw1 = (const float*)d_in[8];
    const float* fb1 = (const float*)d_in[9];
    const float* fw2 = (const float*)d_in[10];
    const float* fb2 = (const float*)d_in[11];
    float* out = (float*)d_out;

    float* hA;
    cudaGetSymbolAddress((void**)&hA, g_hA);

    const int NB_N  = (NN + 255) / 256;        // 196
    const int NB_E4 = (EE / 4 + 255) / 256;    // 782

    init_kernel<<<NB_N, 256>>>();
    count_kernel<<<NB_E4, 256>>>(ei);
    alloc_kernel<<<NB_N, 256>>>();
    scatter_kernel<<<NB_E4, 256>>>(ei);

    const int GB = (NN + 127) / 128;           // 391

    gemm_kernel<DIN><<<GB, 128>>>(x,  W1, NN);
    agg_kernel<<<AB, 256>>>(b1);
    gemm_kernel<HH><<<GB, 128>>>(hA, W2, NN);
    agg_kernel<<<AB, 256>>>(b2);
    gemm_kernel<HH><<<GB, 128>>>(hA, W3, NN);
    agg_pool_kernel<<<AB, 256>>>(b3);

    pool_reduce_kernel<<<32, 256>>>();
    head_kernel<<<1, 64>>>(fw1, fb1, fw2, fb2, out);
}

// round 4
// speedup vs baseline: 1.3115x; 1.0206x over previous
#include <cuda_runtime.h>
#include <cuda_fp16.h>

#define NN   50000
#define EE   800000
#define DIN  128
#define HH   64
#define AB   6250                 // agg blocks: 8 rows x 6250 = 50000 exactly
#define CAP  (EE + 4 * NN)        // CSR capacity incl. per-row pad to multiple of 4

// ---------------- scratch (static device globals: no allocation) -------------
__device__ int    g_deg[NN];
__device__ int2   g_row[NN];                 // (rowstart, real deg)
__device__ int    g_tot;
__device__ float  g_dinv[NN];
__device__ int    g_rank[EE];                // edge rank within dst segment
__device__ int2   g_colval[CAP];             // (src, bits(dinv[src])); pads are 0
__device__ __align__(16) __half g_hH[(size_t)NN * HH];   // gemm out (raw h, fp16)
__device__ __align__(16) float  g_hA[(size_t)NN * HH];   // agg out, fp32
__device__ float2 g_psT[32 * AB];            // pool sum partials [lanecol][blk]
__device__ float2 g_pmT[32 * AB];            // pool max partials
__device__ float  g_poolS[HH];
__device__ float  g_poolM[HH];

typedef unsigned long long u64;

__device__ __forceinline__ void ffma2(u64& d, u64 a, u64 b) {
    asm("fma.rn.f32x2 %0, %1, %2, %0;" : "+l"(d) : "l"(a), "l"(b));
}
__device__ __forceinline__ u64 pack2(float lo, float hi) {
    u64 r; asm("mov.b64 %0, {%1, %2};" : "=l"(r) : "f"(lo), "f"(hi)); return r;
}
__device__ __forceinline__ void unpack2(float& lo, float& hi, u64 v) {
    asm("mov.b64 {%0, %1}, %2;" : "=f"(lo), "=f"(hi) : "l"(v));
}

// ---------------- setup kernels ----------------------------------------------
// zero deg, tot, and the whole padded CSR array (pad slots must read as w=0)
__global__ void init_kernel() {
    int i = blockIdx.x * blockDim.x + threadIdx.x;
    if (i < NN) g_deg[i] = 0;
    if (i == 0) g_tot = 0;
    if (i < CAP / 2) reinterpret_cast<int4*>(g_colval)[i] = make_int4(0, 0, 0, 0);
}

// histogram; atomic return value doubles as the edge's rank within its segment
__global__ void count_kernel(const int* __restrict__ ei) {
    int i = blockIdx.x * blockDim.x + threadIdx.x;
    if (i >= EE / 4) return;
    int4 d4 = reinterpret_cast<const int4*>(ei + EE)[i];
    int4 r4;
    r4.x = atomicAdd(&g_deg[d4.x], 1);
    r4.y = atomicAdd(&g_deg[d4.y], 1);
    r4.z = atomicAdd(&g_deg[d4.z], 1);
    r4.w = atomicAdd(&g_deg[d4.w], 1);
    reinterpret_cast<int4*>(g_rank)[i] = r4;
}

// warp-aggregated segment allocator (pads each segment to a multiple of 4) + dinv
__global__ void alloc_kernel() {
    int i    = blockIdx.x * blockDim.x + threadIdx.x;
    int lane = threadIdx.x & 31;
    int d    = (i < NN) ? g_deg[i] : 0;
    int pd   = (d + 3) & ~3;

    int x = pd;
#pragma unroll
    for (int off = 1; off < 32; off <<= 1) {
        int v = __shfl_up_sync(0xFFFFFFFFu, x, off);
        if (lane >= off) x += v;
    }
    int wsum = __shfl_sync(0xFFFFFFFFu, x, 31);
    int base = 0;
    if (lane == 31) base = atomicAdd(&g_tot, wsum);
    base = __shfl_sync(0xFFFFFFFFu, base, 31);

    if (i < NN) {
        g_row[i]  = make_int2(base + x - pd, d);
        g_dinv[i] = rsqrtf((float)d + 1.0f);
    }
}

// atomic-free scatter: slot = rowstart[dst] + rank[e]; store (src, dinv[src])
__global__ void scatter_kernel(const int* __restrict__ ei) {
    int i = blockIdx.x * blockDim.x + threadIdx.x;
    if (i >= EE / 4) return;
    int4 s4 = reinterpret_cast<const int4*>(ei)[i];
    int4 d4 = reinterpret_cast<const int4*>(ei + EE)[i];
    int4 r4 = reinterpret_cast<const int4*>(g_rank)[i];
    g_colval[g_row[d4.x].x + r4.x] = make_int2(s4.x, __float_as_int(g_dinv[s4.x]));
    g_colval[g_row[d4.y].x + r4.y] = make_int2(s4.y, __float_as_int(g_dinv[s4.y]));
    g_colval[g_row[d4.z].x + r4.z] = make_int2(s4.z, __float_as_int(g_dinv[s4.z]));
    g_colval[g_row[d4.w].x + r4.w] = make_int2(s4.w, __float_as_int(g_dinv[s4.w]));
}

// ---------------- GEMM: hH[N,64] = fp16( X[N,K] @ W[K,64] ) ------------------
// one thread per row, 32 packed f32x2 accumulators, W broadcast from smem.
// No graph dependency: raw (unscaled) h is stored; dinv applied in agg.
template <int K>
__global__ __launch_bounds__(128) void gemm_kernel(const float* __restrict__ X,
                                                   const float* __restrict__ W,
                                                   int nrows) {
    __shared__ ulonglong2 Wsm[K * 16];        // K x 64 floats as 16B chunks
    for (int i = threadIdx.x; i < K * 16; i += 128)
        Wsm[i] = reinterpret_cast<const ulonglong2*>(W)[i];
    __syncthreads();

    int row = blockIdx.x * 128 + threadIdx.x;
    if (row >= nrows) return;

    const float4* xp = reinterpret_cast<const float4*>(X + (size_t)row * K);
    u64 acc[32];
#pragma unroll
    for (int c = 0; c < 32; c++) acc[c] = 0ull;

#pragma unroll 1
    for (int kc = 0; kc < K / 16; kc++) {
        float4 xv[4];
#pragma unroll
        for (int j = 0; j < 4; j++) xv[j] = xp[kc * 4 + j];
#pragma unroll
        for (int j = 0; j < 4; j++) {
            const float xs[4] = {xv[j].x, xv[j].y, xv[j].z, xv[j].w};
#pragma unroll
            for (int q = 0; q < 4; q++) {
                const u64 ss = pack2(xs[q], xs[q]);
                const int k  = kc * 16 + j * 4 + q;
#pragma unroll
                for (int c = 0; c < 16; c++) {
                    ulonglong2 w = Wsm[k * 16 + c];
                    ffma2(acc[2 * c],     ss, w.x);
                    ffma2(acc[2 * c + 1], ss, w.y);
                }
            }
        }
    }

    uint4* yp = reinterpret_cast<uint4*>((char*)g_hH + (size_t)row * 128);
#pragma unroll
    for (int c = 0; c < 8; c++) {
        uint4 o;
        unsigned r[4];
#pragma unroll
        for (int q = 0; q < 4; q++) {
            float lo, hi;
            unpack2(lo, hi, acc[4 * c + q]);
            __half2 h = __floats2half2_rn(lo, hi);
            r[q] = *reinterpret_cast<unsigned*>(&h);
        }
        o.x = r[0]; o.y = r[1]; o.z = r[2]; o.w = r[3];
        yp[c] = o;
    }
}

// ---------------- aggregation: warp per node, fp16 gather --------------------
// A[i] = relu( dinv_i * sum_j dinv_j*h_j + dinv_i^2 * h_i + b )
__device__ __forceinline__ float2 agg_row(int row, int lane) {
    int2 rd     = g_row[row];
    int  padded = (rd.y + 3) & ~3;            // pad slots hold (0, 0.0f)
    const unsigned* hb = reinterpret_cast<const unsigned*>(g_hH);

    float ax = 0.f, ay = 0.f;
    for (int base = 0; base < padded; base += 32) {
        int cnt = min(32, padded - base);
        int2 cv = make_int2(0, 0);
        if (lane < cnt) cv = g_colval[rd.x + base + lane];
        for (int j = 0; j < cnt; j += 4) {
#pragma unroll
            for (int q = 0; q < 4; q++) {
                int   sj = __shfl_sync(0xFFFFFFFFu, cv.x, j + q);
                float wj = __int_as_float(__shfl_sync(0xFFFFFFFFu, cv.y, j + q));
                unsigned hv = __ldg(hb + sj * 32 + lane);
                float2 f = __half22float2(*reinterpret_cast<__half2*>(&hv));
                ax = fmaf(wj, f.x, ax);
                ay = fmaf(wj, f.y, ay);
            }
        }
    }
    return make_float2(ax, ay);
}

__device__ __forceinline__ float2 agg_finish(int row, int lane, float2 a,
                                             const float* bias) {
    const unsigned* hb = reinterpret_cast<const unsigned*>(g_hH);
    unsigned hs = hb[row * 32 + lane];
    float2 fs = __half22float2(*reinterpret_cast<__half2*>(&hs));
    float di  = g_dinv[row];
    float di2 = di * di;
    float2 b = reinterpret_cast<const float2*>(bias)[lane];
    float ox = fmaf(di, a.x, fmaf(di2, fs.x, b.x));
    float oy = fmaf(di, a.y, fmaf(di2, fs.y, b.y));
    return make_float2(fmaxf(ox, 0.f), fmaxf(oy, 0.f));
}

__global__ void agg_kernel(const float* __restrict__ bias) {
    int warp = threadIdx.x >> 5;
    int lane = threadIdx.x & 31;
    int row  = blockIdx.x * 8 + warp;
    float2 a = agg_row(row, lane);
    float2 o = agg_finish(row, lane, a, bias);
    reinterpret_cast<float2*>(g_hA)[row * 32 + lane] = o;
}

// layer-3 agg with fused pooling partials (activations never materialized)
__global__ void agg_pool_kernel(const float* __restrict__ bias) {
    __shared__ float2 s_sum[8][32];
    __shared__ float2 s_max[8][32];
    int warp = threadIdx.x >> 5;
    int lane = threadIdx.x & 31;
    int row  = blockIdx.x * 8 + warp;

    float2 a = agg_row(row, lane);
    float2 o = agg_finish(row, lane, a, bias);
    s_sum[warp][lane] = o;
    s_max[warp][lane] = o;
    __syncthreads();

    if (threadIdx.x < 32) {
        float2 S = make_float2(0.f, 0.f), M = make_float2(0.f, 0.f);
#pragma unroll
        for (int w = 0; w < 8; w++) {
            float2 v = s_sum[w][threadIdx.x];
            S.x += v.x; S.y += v.y;
            float2 m = s_max[w][threadIdx.x];
            M.x = fmaxf(M.x, m.x); M.y = fmaxf(M.y, m.y);
        }
        g_psT[threadIdx.x * AB + blockIdx.x] = S;   // transposed: coalesced reduce
        g_pmT[threadIdx.x * AB + blockIdx.x] = M;
    }
}

// collapse 6250 partials per lane-column pair (32 blocks, coalesced reads)
__global__ void pool_reduce_kernel() {
    __shared__ float sx[256], sy[256], mx[256], my[256];
    int c   = blockIdx.x;
    int tid = threadIdx.x;
    float ax = 0.f, ay = 0.f, bx = 0.f, by = 0.f;
    for (int i = tid; i < AB; i += 256) {
        float2 s = g_psT[c * AB + i];
        ax += s.x; ay += s.y;
        float2 m = g_pmT[c * AB + i];
        bx = fmaxf(bx, m.x); by = fmaxf(by, m.y);
    }
    sx[tid] = ax; sy[tid] = ay; mx[tid] = bx; my[tid] = by;
    __syncthreads();
    for (int off = 128; off > 0; off >>= 1) {
        if (tid < off) {
            sx[tid] += sx[tid + off]; sy[tid] += sy[tid + off];
            mx[tid] = fmaxf(mx[tid], mx[tid + off]);
            my[tid] = fmaxf(my[tid], my[tid + off]);
        }
        __syncthreads();
    }
    if (tid == 0) {
        g_poolS[2 * c]     = sx[0]; g_poolS[2 * c + 1] = sy[0];
        g_poolM[2 * c]     = mx[0]; g_poolM[2 * c + 1] = my[0];
    }
}

__global__ void head_kernel(const float* __restrict__ fw1,
                            const float* __restrict__ fb1,
                            const float* __restrict__ fw2,
                            const float* __restrict__ fb2,
                            float* __restrict__ out) {
    __shared__ float pooled[128];
    __shared__ float red[64];
    int tid = threadIdx.x;                    // 64 threads
    pooled[tid]      = g_poolS[tid] * (1.0f / NN);
    pooled[tid + 64] = g_poolM[tid];
    __syncthreads();

    float acc = fb1[tid];
#pragma unroll 4
    for (int k = 0; k < 128; k++) acc = fmaf(pooled[k], fw1[k * 64 + tid], acc);
    red[tid] = fmaxf(acc, 0.f) * fw2[tid];
    __syncthreads();
    if (tid == 0) {
        float t = 0.f;
        for (int i = 0; i < 64; i++) t += red[i];
        out[0] = t + fb2[0];
    }
}

// ---------------- launcher ---------------------------------------------------
extern "C" void kernel_launch(void* const* d_in, const int* in_sizes, int n_in,
                              void* d_out, int out_size) {
    const float* x   = (const float*)d_in[0];
    const int*   ei  = (const int*)d_in[1];
    const float* W1  = (const float*)d_in[2];
    const float* b1  = (const float*)d_in[3];
    const float* W2  = (const float*)d_in[4];
    const float* b2  = (const float*)d_in[5];
    const float* W3  = (const float*)d_in[6];
    const float* b3  = (const float*)d_in[7];
    const float* fw1 = (const float*)d_in[8];
    const float* fb1 = (const float*)d_in[9];
    const float* fw2 = (const float*)d_in[10];
    const float* fb2 = (const float*)d_in[11];
    float* out = (float*)d_out;

    float* hA;
    cudaGetSymbolAddress((void**)&hA, g_hA);

    // side stream + events for the CSR-build / GEMM1 overlap (host-side
    // resources only; created once, reused — no device memory involved)
    static cudaStream_t sB = nullptr;
    static cudaEvent_t  eF = nullptr, eJ = nullptr;
    if (sB == nullptr) {
        cudaStreamCreateWithFlags(&sB, cudaStreamNonBlocking);
        cudaEventCreateWithFlags(&eF, cudaEventDisableTiming);
        cudaEventCreateWithFlags(&eJ, cudaEventDisableTiming);
    }

    const int NB_I  = (CAP / 2 + 255) / 256;   // 1954 (covers NN and CAP/2)
    const int NB_N  = (NN + 255) / 256;        // 196
    const int NB_E4 = (EE / 4 + 255) / 256;    // 782
    const int GB    = (NN + 127) / 128;        // 391

    // fork: GEMM1 (depends only on x, W1) runs on sB concurrently with CSR build
    cudaEventRecord(eF, 0);
    cudaStreamWaitEvent(sB, eF, 0);
    gemm_kernel<DIN><<<GB, 128, 0, sB>>>(x, W1, NN);
    cudaEventRecord(eJ, sB);

    // CSR build on the main stream
    init_kernel<<<NB_I, 256>>>();
    count_kernel<<<NB_E4, 256>>>(ei);
    alloc_kernel<<<NB_N, 256>>>();
    scatter_kernel<<<NB_E4, 256>>>(ei);

    // join: agg1 needs both CSR and GEMM1
    cudaStreamWaitEvent(0, eJ, 0);

    agg_kernel<<<AB, 256>>>(b1);
    gemm_kernel<HH><<<GB, 128>>>(hA, W2, NN);
    agg_kernel<<<AB, 256>>>(b2);
    gemm_kernel<HH><<<GB, 128>>>(hA, W3, NN);
    agg_pool_kernel<<<AB, 256>>>(b3);

    pool_reduce_kernel<<<32, 256>>>();
    head_kernel<<<1, 64>>>(fw1, fb1, fw2, fb2, out);
}

// round 5
// speedup vs baseline: 1.3851x; 1.0561x over previous
#include <cuda_runtime.h>
#include <cuda_fp16.h>

#define NN   50000
#define EE   800000
#define DIN  128
#define HH   64
#define AB   6250                 // agg blocks: 8 rows x 6250 = 50000 exactly
#define CAP  (EE + 4 * NN)        // padded CSR capacity (1,000,000; mult of 4)

// ---------------- scratch (static device globals: no allocation) -------------
__device__ int    g_deg[NN];
__device__ int2   g_row[NN];                 // (rowstart, real deg)
__device__ int    g_tot;
__device__ float  g_dinv[NN];
__device__ int    g_rank[EE];                // edge rank within dst segment
__device__ int    g_col[CAP];                // src per CSR slot; pads = NN (dummy)
__device__ __align__(16) __half g_hH[(size_t)(NN + 1) * HH]; // h' = dinv*h (fp16); row NN = 0
__device__ __align__(16) float  g_hA[(size_t)NN * HH];       // agg out, fp32
__device__ float2 g_psT[32 * AB];            // pool sum partials [lanecol][blk]
__device__ float2 g_pmT[32 * AB];            // pool max partials
__device__ float  g_poolS[HH];
__device__ float  g_poolM[HH];

typedef unsigned long long u64;

__device__ __forceinline__ void ffma2(u64& d, u64 a, u64 b) {
    asm("fma.rn.f32x2 %0, %1, %2, %0;" : "+l"(d) : "l"(a), "l"(b));
}
__device__ __forceinline__ u64 pack2(float lo, float hi) {
    u64 r; asm("mov.b64 %0, {%1, %2};" : "=l"(r) : "f"(lo), "f"(hi)); return r;
}
__device__ __forceinline__ void unpack2(float& lo, float& hi, u64 v) {
    asm("mov.b64 {%0, %1}, %2;" : "=f"(lo), "=f"(hi) : "l"(v));
}

// ---------------- setup kernels ----------------------------------------------
// zero deg/tot/dummy-row; fill g_col with NN so pad slots gather zeros
__global__ void init_kernel() {
    int i = blockIdx.x * blockDim.x + threadIdx.x;
    if (i < NN) g_deg[i] = 0;
    if (i == 0) g_tot = 0;
    if (i < 8) reinterpret_cast<int4*>(g_hH + (size_t)NN * HH)[i] = make_int4(0, 0, 0, 0);
    if (i < CAP / 4) reinterpret_cast<int4*>(g_col)[i] = make_int4(NN, NN, NN, NN);
}

// histogram; atomic return value doubles as the edge's rank within its segment
__global__ void count_kernel(const int* __restrict__ ei) {
    int i = blockIdx.x * blockDim.x + threadIdx.x;
    if (i >= EE / 4) return;
    int4 d4 = reinterpret_cast<const int4*>(ei + EE)[i];
    int4 r4;
    r4.x = atomicAdd(&g_deg[d4.x], 1);
    r4.y = atomicAdd(&g_deg[d4.y], 1);
    r4.z = atomicAdd(&g_deg[d4.z], 1);
    r4.w = atomicAdd(&g_deg[d4.w], 1);
    reinterpret_cast<int4*>(g_rank)[i] = r4;
}

// warp-aggregated segment allocator (pads each segment to a multiple of 4) + dinv
__global__ void alloc_kernel() {
    int i    = blockIdx.x * blockDim.x + threadIdx.x;
    int lane = threadIdx.x & 31;
    int d    = (i < NN) ? g_deg[i] : 0;
    int pd   = (d + 3) & ~3;

    int x = pd;
#pragma unroll
    for (int off = 1; off < 32; off <<= 1) {
        int v = __shfl_up_sync(0xFFFFFFFFu, x, off);
        if (lane >= off) x += v;
    }
    int wsum = __shfl_sync(0xFFFFFFFFu, x, 31);
    int base = 0;
    if (lane == 31) base = atomicAdd(&g_tot, wsum);
    base = __shfl_sync(0xFFFFFFFFu, base, 31);

    if (i < NN) {
        g_row[i]  = make_int2(base + x - pd, d);
        g_dinv[i] = rsqrtf((float)d + 1.0f);
    }
}

// atomic-free scatter: slot = rowstart[dst] + rank[e]
__global__ void scatter_kernel(const int* __restrict__ ei) {
    int i = blockIdx.x * blockDim.x + threadIdx.x;
    if (i >= EE / 4) return;
    int4 s4 = reinterpret_cast<const int4*>(ei)[i];
    int4 d4 = reinterpret_cast<const int4*>(ei + EE)[i];
    int4 r4 = reinterpret_cast<const int4*>(g_rank)[i];
    g_col[g_row[d4.x].x + r4.x] = s4.x;
    g_col[g_row[d4.y].x + r4.y] = s4.y;
    g_col[g_row[d4.z].x + r4.z] = s4.z;
    g_col[g_row[d4.w].x + r4.w] = s4.w;
}

// ---------------- GEMM: hH[N,64] = fp16( dinv[i] * (X[N,K] @ W[K,64]) ) ------
// one thread per row, 32 packed f32x2 accumulators, W broadcast from smem.
template <int K>
__global__ __launch_bounds__(128) void gemm_kernel(const float* __restrict__ X,
                                                   const float* __restrict__ W,
                                                   int nrows) {
    __shared__ ulonglong2 Wsm[K * 16];        // K x 64 floats as 16B chunks
    for (int i = threadIdx.x; i < K * 16; i += 128)
        Wsm[i] = reinterpret_cast<const ulonglong2*>(W)[i];
    __syncthreads();

    int row = blockIdx.x * 128 + threadIdx.x;
    if (row >= nrows) return;

    const float4* xp = reinterpret_cast<const float4*>(X + (size_t)row * K);
    u64 acc[32];
#pragma unroll
    for (int c = 0; c < 32; c++) acc[c] = 0ull;

#pragma unroll 1
    for (int kc = 0; kc < K / 16; kc++) {
        float4 xv[4];
#pragma unroll
        for (int j = 0; j < 4; j++) xv[j] = xp[kc * 4 + j];
#pragma unroll
        for (int j = 0; j < 4; j++) {
            const float xs[4] = {xv[j].x, xv[j].y, xv[j].z, xv[j].w};
#pragma unroll
            for (int q = 0; q < 4; q++) {
                const u64 ss = pack2(xs[q], xs[q]);
                const int k  = kc * 16 + j * 4 + q;
#pragma unroll
                for (int c = 0; c < 16; c++) {
                    ulonglong2 w = Wsm[k * 16 + c];
                    ffma2(acc[2 * c],     ss, w.x);
                    ffma2(acc[2 * c + 1], ss, w.y);
                }
            }
        }
    }

    // epilogue: scale by dinv[row], convert to fp16, store 128B row
    float di = g_dinv[row];
    uint4* yp = reinterpret_cast<uint4*>((char*)g_hH + (size_t)row * 128);
#pragma unroll
    for (int c = 0; c < 8; c++) {
        uint4 o;
        unsigned r[4];
#pragma unroll
        for (int q = 0; q < 4; q++) {
            float lo, hi;
            unpack2(lo, hi, acc[4 * c + q]);
            __half2 h = __floats2half2_rn(lo * di, hi * di);
            r[q] = *reinterpret_cast<unsigned*>(&h);
        }
        o.x = r[0]; o.y = r[1]; o.z = r[2]; o.w = r[3];
        yp[c] = o;
    }
}

// ---------------- aggregation: warp per node, shfl-free fp16 gather ----------
// A[i] = relu( dinv_i * (sum_j h'_j + h'_i) + b ),   h' = dinv*h (fp16)
__device__ __forceinline__ float2 agg_row(int row, int lane) {
    int2 rd     = g_row[row];
    int  padded = (rd.y + 3) & ~3;            // pad slots index dummy zero row
    const int*      cp = g_col + rd.x;
    const unsigned* hb = reinterpret_cast<const unsigned*>(g_hH);

    float ax = 0.f, ay = 0.f;
#pragma unroll 4
    for (int p = 0; p < padded; p++) {
        int sj = __ldg(cp + p);               // warp-uniform broadcast load
        unsigned hv = __ldg(hb + sj * 32 + lane);
        float2 f = __half22float2(*reinterpret_cast<__half2*>(&hv));
        ax += f.x;
        ay += f.y;
    }
    return make_float2(ax, ay);
}

__device__ __forceinline__ float2 agg_finish(int row, int lane, float2 a,
                                             const float* bias) {
    const unsigned* hb = reinterpret_cast<const unsigned*>(g_hH);
    unsigned hs = hb[row * 32 + lane];
    float2 fs = __half22float2(*reinterpret_cast<__half2*>(&hs));
    float di = g_dinv[row];
    float2 b = reinterpret_cast<const float2*>(bias)[lane];
    float ox = fmaf(di, a.x + fs.x, b.x);
    float oy = fmaf(di, a.y + fs.y, b.y);
    return make_float2(fmaxf(ox, 0.f), fmaxf(oy, 0.f));
}

__global__ void agg_kernel(const float* __restrict__ bias) {
    int warp = threadIdx.x >> 5;
    int lane = threadIdx.x & 31;
    int row  = blockIdx.x * 8 + warp;
    float2 a = agg_row(row, lane);
    float2 o = agg_finish(row, lane, a, bias);
    reinterpret_cast<float2*>(g_hA)[row * 32 + lane] = o;
}

// layer-3 agg with fused pooling partials (activations never materialized)
__global__ void agg_pool_kernel(const float* __restrict__ bias) {
    __shared__ float2 s_sum[8][32];
    __shared__ float2 s_max[8][32];
    int warp = threadIdx.x >> 5;
    int lane = threadIdx.x & 31;
    int row  = blockIdx.x * 8 + warp;

    float2 a = agg_row(row, lane);
    float2 o = agg_finish(row, lane, a, bias);
    s_sum[warp][lane] = o;
    s_max[warp][lane] = o;
    __syncthreads();

    if (threadIdx.x < 32) {
        float2 S = make_float2(0.f, 0.f), M = make_float2(0.f, 0.f);
#pragma unroll
        for (int w = 0; w < 8; w++) {
            float2 v = s_sum[w][threadIdx.x];
            S.x += v.x; S.y += v.y;
            float2 m = s_max[w][threadIdx.x];
            M.x = fmaxf(M.x, m.x); M.y = fmaxf(M.y, m.y);
        }
        g_psT[threadIdx.x * AB + blockIdx.x] = S;   // transposed: coalesced reduce
        g_pmT[threadIdx.x * AB + blockIdx.x] = M;
    }
}

// collapse 6250 partials per lane-column pair (32 blocks, coalesced reads)
__global__ void pool_reduce_kernel() {
    __shared__ float sx[256], sy[256], mx[256], my[256];
    int c   = blockIdx.x;
    int tid = threadIdx.x;
    float ax = 0.f, ay = 0.f, bx = 0.f, by = 0.f;
    for (int i = tid; i < AB; i += 256) {
        float2 s = g_psT[c * AB + i];
        ax += s.x; ay += s.y;
        float2 m = g_pmT[c * AB + i];
        bx = fmaxf(bx, m.x); by = fmaxf(by, m.y);
    }
    sx[tid] = ax; sy[tid] = ay; mx[tid] = bx; my[tid] = by;
    __syncthreads();
    for (int off = 128; off > 0; off >>= 1) {
        if (tid < off) {
            sx[tid] += sx[tid + off]; sy[tid] += sy[tid + off];
            mx[tid] = fmaxf(mx[tid], mx[tid + off]);
            my[tid] = fmaxf(my[tid], my[tid + off]);
        }
        __syncthreads();
    }
    if (tid == 0) {
        g_poolS[2 * c]     = sx[0]; g_poolS[2 * c + 1] = sy[0];
        g_poolM[2 * c]     = mx[0]; g_poolM[2 * c + 1] = my[0];
    }
}

__global__ void head_kernel(const float* __restrict__ fw1,
                            const float* __restrict__ fb1,
                            const float* __restrict__ fw2,
                            const float* __restrict__ fb2,
                            float* __restrict__ out) {
    __shared__ float pooled[128];
    __shared__ float red[64];
    int tid = threadIdx.x;                    // 64 threads
    pooled[tid]      = g_poolS[tid] * (1.0f / NN);
    pooled[tid + 64] = g_poolM[tid];
    __syncthreads();

    float acc = fb1[tid];
#pragma unroll 4
    for (int k = 0; k < 128; k++) acc = fmaf(pooled[k], fw1[k * 64 + tid], acc);
    red[tid] = fmaxf(acc, 0.f) * fw2[tid];
    __syncthreads();
    if (tid == 0) {
        float t = 0.f;
        for (int i = 0; i < 64; i++) t += red[i];
        out[0] = t + fb2[0];
    }
}

// ---------------- launcher ---------------------------------------------------
extern "C" void kernel_launch(void* const* d_in, const int* in_sizes, int n_in,
                              void* d_out, int out_size) {
    const float* x   = (const float*)d_in[0];
    const int*   ei  = (const int*)d_in[1];
    const float* W1  = (const float*)d_in[2];
    const float* b1  = (const float*)d_in[3];
    const float* W2  = (const float*)d_in[4];
    const float* b2  = (const float*)d_in[5];
    const float* W3  = (const float*)d_in[6];
    const float* b3  = (const float*)d_in[7];
    const float* fw1 = (const float*)d_in[8];
    const float* fb1 = (const float*)d_in[9];
    const float* fw2 = (const float*)d_in[10];
    const float* fb2 = (const float*)d_in[11];
    float* out = (float*)d_out;

    float* hA;
    cudaGetSymbolAddress((void**)&hA, g_hA);

    // side stream + events (host-side only; created once, reused)
    static cudaStream_t sB = nullptr;
    static cudaEvent_t  eF = nullptr, eJ = nullptr;
    if (sB == nullptr) {
        cudaStreamCreateWithFlags(&sB, cudaStreamNonBlocking);
        cudaEventCreateWithFlags(&eF, cudaEventDisableTiming);
        cudaEventCreateWithFlags(&eJ, cudaEventDisableTiming);
    }

    const int NB_I  = (CAP / 4 + 255) / 256;   // 977 (covers NN and CAP/4)
    const int NB_N  = (NN + 255) / 256;        // 196
    const int NB_E4 = (EE / 4 + 255) / 256;    // 782
    const int GB    = (NN + 127) / 128;        // 391

    // CSR build (through alloc) on the main stream
    init_kernel<<<NB_I, 256>>>();
    count_kernel<<<NB_E4, 256>>>(ei);
    alloc_kernel<<<NB_N, 256>>>();

    // fork: GEMM1 (needs dinv from alloc) runs on sB concurrently with scatter
    cudaEventRecord(eF, 0);
    cudaStreamWaitEvent(sB, eF, 0);
    gemm_kernel<DIN><<<GB, 128, 0, sB>>>(x, W1, NN);
    cudaEventRecord(eJ, sB);

    scatter_kernel<<<NB_E4, 256>>>(ei);

    // join: agg1 needs both CSR and GEMM1
    cudaStreamWaitEvent(0, eJ, 0);

    agg_kernel<<<AB, 256>>>(b1);
    gemm_kernel<HH><<<GB, 128>>>(hA, W2, NN);
    agg_kernel<<<AB, 256>>>(b2);
    gemm_kernel<HH><<<GB, 128>>>(hA, W3, NN);
    agg_pool_kernel<<<AB, 256>>>(b3);

    pool_reduce_kernel<<<32, 256>>>();
    head_kernel<<<1, 64>>>(fw1, fb1, fw2, fb2, out);
}